// round 12
// baseline (speedup 1.0000x reference)
#include <cuda_runtime.h>
#include <cuda_bf16.h>

#define N_SRC   100000
#define N_DST   100000
#define N_EDGES 1250000
#define D_FEAT  64
#define HIDDEN  64
#define OUTD    128
#define CAP     48      // P(Poisson(12.5) > 48) ~ 1e-14 per bin

// Scratch (alloc-free rule: __device__ globals)
__device__ float              g_hs[N_SRC * HIDDEN];
__device__ int                g_cnt[N_DST];
__device__ unsigned long long g_bkt[(size_t)N_DST * CAP];   // (w_bits<<32 | src)
__device__ unsigned int       g_xhi[(size_t)N_DST * 64];    // X hi-plane, bf16x2 words
__device__ unsigned int       g_xlo[(size_t)N_DST * 64];    // X lo-plane
__device__ unsigned int       g_w2hi[OUTD * 64];            // W2^T hi-plane [n][kw]
__device__ unsigned int       g_w2lo[OUTD * 64];
__device__ double             g_ssq;

__device__ __forceinline__ unsigned int packbf2(float a, float b) {
    __nv_bfloat162 t = __floats2bfloat162_rn(a, b);   // a -> low half
    return *(unsigned int*)&t;
}

__device__ __forceinline__ void mma_bf16(float* c, const unsigned int* a,
                                         unsigned int b0, unsigned int b1) {
    asm volatile(
        "mma.sync.aligned.m16n8k16.row.col.f32.bf16.bf16.f32 "
        "{%0,%1,%2,%3}, {%4,%5,%6,%7}, {%8,%9}, {%0,%1,%2,%3};"
        : "+f"(c[0]), "+f"(c[1]), "+f"(c[2]), "+f"(c[3])
        : "r"(a[0]), "r"(a[1]), "r"(a[2]), "r"(a[3]), "r"(b0), "r"(b1));
}

// ---------------------------------------------------------------------------
// K0: zero counts/ssq + convert W2^T to bf16 hi/lo planes (once).
// ---------------------------------------------------------------------------
__global__ void k_prep(const float* __restrict__ W2) {
    const int gt = blockIdx.x * blockDim.x + threadIdx.x;
    const int gs = gridDim.x * blockDim.x;
    for (int i = gt; i < N_DST / 4; i += gs)
        ((int4*)g_cnt)[i] = make_int4(0, 0, 0, 0);
    for (int i = gt; i < OUTD * 64; i += gs) {
        const int n = i >> 6, kw = i & 63;
        const float w0 = W2[(2 * kw) * OUTD + n];
        const float w1 = W2[(2 * kw + 1) * OUTD + n];
        const float h0 = __bfloat162float(__float2bfloat16(w0));
        const float h1 = __bfloat162float(__float2bfloat16(w1));
        g_w2hi[i] = packbf2(h0, h1);
        g_w2lo[i] = packbf2(w0 - h0, w1 - h1);
    }
    if (gt == 0) g_ssq = 0.0;
}

// ---------------------------------------------------------------------------
// K1: hs = relu(h_src @ W1 + b1). 64-row tiles; thread = 4 rows x 4 outputs:
// per k one LDS.128 (W1) + 4 broadcast LDS + 16 FFMA -> FMA-bound.
// ---------------------------------------------------------------------------
__global__ void k_fc1(const float* __restrict__ h_src,
                      const float* __restrict__ W1,
                      const float* __restrict__ b1) {
    __shared__ float w1s[D_FEAT * HIDDEN];   // [k][o]
    __shared__ float b1s[HIDDEN];
    __shared__ float xs[64 * 68];            // [row][k], pad 68

    const int tid = threadIdx.x;
    for (int i = tid; i < D_FEAT * HIDDEN; i += blockDim.x) w1s[i] = W1[i];
    if (tid < HIDDEN) b1s[tid] = b1[tid];

    const int base = blockIdx.x * 64;
    for (int i = tid; i < 64 * 64; i += blockDim.x) {
        const int row = i >> 6, k = i & 63;
        const int rr = base + row;
        xs[row * 68 + k] = (rr < N_SRC) ? h_src[(size_t)rr * D_FEAT + k] : 0.0f;
    }
    __syncthreads();

    const int og   = tid & 15;    // output group: cols og*4..+3
    const int rgrp = tid >> 4;    // row group: rows rgrp*4..+3
    float acc[4][4];
    #pragma unroll
    for (int j = 0; j < 4; j++)
        #pragma unroll
        for (int q = 0; q < 4; q++) acc[j][q] = b1s[og * 4 + q];

    #pragma unroll 16
    for (int k = 0; k < D_FEAT; k++) {
        const float4 w4 = *(const float4*)&w1s[k * HIDDEN + og * 4];
        #pragma unroll
        for (int j = 0; j < 4; j++) {
            const float x = xs[(rgrp * 4 + j) * 68 + k];
            acc[j][0] = fmaf(x, w4.x, acc[j][0]);
            acc[j][1] = fmaf(x, w4.y, acc[j][1]);
            acc[j][2] = fmaf(x, w4.z, acc[j][2]);
            acc[j][3] = fmaf(x, w4.w, acc[j][3]);
        }
    }
    #pragma unroll
    for (int j = 0; j < 4; j++) {
        const int row = base + rgrp * 4 + j;
        if (row < N_SRC) {
            float4 o;
            o.x = fmaxf(acc[j][0], 0.0f);
            o.y = fmaxf(acc[j][1], 0.0f);
            o.z = fmaxf(acc[j][2], 0.0f);
            o.w = fmaxf(acc[j][3], 0.0f);
            *(float4*)&g_hs[(size_t)row * HIDDEN + og * 4] = o;
        }
    }
}

// ---------------------------------------------------------------------------
// K2: bucket edges by destination (int atomics only)   (R4-proven)
// ---------------------------------------------------------------------------
__global__ void k_bucket(const float* __restrict__ ew,
                         const int*   __restrict__ src_idx,
                         const int*   __restrict__ dst_idx) {
    const int e = blockIdx.x * blockDim.x + threadIdx.x;
    if (e >= N_EDGES) return;
    const int   s = __ldg(src_idx + e);
    const int   d = __ldg(dst_idx + e);
    const float w = __ldg(ew + e);
    const int slot = atomicAdd(&g_cnt[d], 1);
    if (slot < CAP) {
        const unsigned long long p =
            ((unsigned long long)__float_as_uint(w) << 32) | (unsigned int)s;
        g_bkt[(size_t)d * CAP + slot] = p;
    }
}

// ---------------------------------------------------------------------------
// K3: gather-reduce (R4-proven math) -> X bf16 hi/lo planes in global.
// Warp handles 4 dsts; no block syncs.
// ---------------------------------------------------------------------------
__global__ void k_gather(const float* __restrict__ h_dst) {
    const int warp = threadIdx.x >> 5;
    const int lane = threadIdx.x & 31;

    for (int base = (blockIdx.x * 8 + warp) * 4; base < N_DST;
         base += gridDim.x * 8 * 4) {
        int n[4];
        unsigned long long e0[4], e1[4];
        #pragma unroll
        for (int r = 0; r < 4; r++) {
            const int dst = base + r;
            int c = __ldg(&g_cnt[dst]);
            n[r] = (c > CAP) ? CAP : c;
            const unsigned long long* bkt = g_bkt + (size_t)dst * CAP;
            e0[r] = (lane      < n[r]) ? __ldg(bkt + lane)      : 0ull;
            e1[r] = (lane + 32 < n[r]) ? __ldg(bkt + lane + 32) : 0ull;
        }
        #pragma unroll
        for (int r = 0; r < 4; r++) {
            float ax = 0.0f, ay = 0.0f, wsum = 0.0f;
            const int n0 = (n[r] < 32) ? n[r] : 32;
            for (int i = 0; i < n0; i++) {
                const unsigned long long p = __shfl_sync(0xFFFFFFFFu, e0[r], i);
                const float w = __uint_as_float((unsigned int)(p >> 32));
                const int   s = (int)(p & 0xffffffffu);
                const float2 v = __ldg(((const float2*)(g_hs + (size_t)s * HIDDEN)) + lane);
                ax = fmaf(v.x, w, ax);
                ay = fmaf(v.y, w, ay);
                wsum += w;
            }
            for (int i = 32; i < n[r]; i++) {
                const unsigned long long p = __shfl_sync(0xFFFFFFFFu, e1[r], i - 32);
                const float w = __uint_as_float((unsigned int)(p >> 32));
                const int   s = (int)(p & 0xffffffffu);
                const float2 v = __ldg(((const float2*)(g_hs + (size_t)s * HIDDEN)) + lane);
                ax = fmaf(v.x, w, ax);
                ay = fmaf(v.y, w, ay);
                wsum += w;
            }
            const int dst = base + r;
            const float inv = 1.0f / fmaxf(wsum, 1.0f);
            const float vx = ax * inv, vy = ay * inv;
            const float2 hd = __ldg(((const float2*)(h_dst + (size_t)dst * D_FEAT)) + lane);
            const float hx = __bfloat162float(__float2bfloat16(vx));
            const float hy = __bfloat162float(__float2bfloat16(vy));
            const float dx = __bfloat162float(__float2bfloat16(hd.x));
            const float dy = __bfloat162float(__float2bfloat16(hd.y));
            // word kw packs cols 2kw,2kw+1: nv -> words [0,32), h_dst -> [32,64)
            g_xhi[(size_t)dst * 64 + lane]      = packbf2(hx, hy);
            g_xlo[(size_t)dst * 64 + lane]      = packbf2(vx - hx, vy - hy);
            g_xhi[(size_t)dst * 64 + 32 + lane] = packbf2(dx, dy);
            g_xlo[(size_t)dst * 64 + 32 + lane] = packbf2(hd.x - dx, hd.y - dy);
        }
    }
}

// ---------------------------------------------------------------------------
// K4: fc2 streaming GEMM: out = relu(X @ W2 + b2), ssq accumulate.
// Block = 64-row tile; warp = 16 rows x 64 cols; bf16 mma 3-term split.
// W2 hi/lo fragments fetched from L2-resident global planes.
// ---------------------------------------------------------------------------
__global__ void k_fc2(const float* __restrict__ b2, float* __restrict__ out) {
    __shared__ unsigned int Xh[64 * 68];   // [row][kw], pad 68
    __shared__ unsigned int Xl[64 * 68];
    __shared__ float b2s[OUTD];
    __shared__ float wssq[8];

    const int tid  = threadIdx.x;
    const int base = blockIdx.x * 64;
    const int rows = (N_DST - base < 64) ? (N_DST - base) : 64;

    for (int i = tid; i < rows * 64; i += blockDim.x) {
        const int row = i >> 6, kw = i & 63;
        Xh[row * 68 + kw] = g_xhi[(size_t)(base + row) * 64 + kw];
        Xl[row * 68 + kw] = g_xlo[(size_t)(base + row) * 64 + kw];
    }
    if (tid < OUTD) b2s[tid] = b2[tid];
    __syncthreads();

    const int warp  = tid >> 5;
    const int lane  = tid & 31;
    const int g     = lane >> 2;
    const int tig   = lane & 3;
    const int mrow  = (warp & 3) * 16;       // row band
    const int nbase = (warp >> 2) * 64;      // col half

    float c[8][4];
    #pragma unroll
    for (int nt = 0; nt < 8; nt++) {
        const int n0 = nbase + nt * 8;
        c[nt][0] = b2s[n0 + 2 * tig];
        c[nt][1] = b2s[n0 + 2 * tig + 1];
        c[nt][2] = c[nt][0];
        c[nt][3] = c[nt][1];
    }

    #pragma unroll
    for (int kt = 0; kt < 8; kt++) {
        const int kw0 = kt * 8;
        unsigned int ah[4], al[4];
        ah[0] = Xh[(mrow + g) * 68 + kw0 + tig];
        ah[1] = Xh[(mrow + g + 8) * 68 + kw0 + tig];
        ah[2] = Xh[(mrow + g) * 68 + kw0 + tig + 4];
        ah[3] = Xh[(mrow + g + 8) * 68 + kw0 + tig + 4];
        al[0] = Xl[(mrow + g) * 68 + kw0 + tig];
        al[1] = Xl[(mrow + g + 8) * 68 + kw0 + tig];
        al[2] = Xl[(mrow + g) * 68 + kw0 + tig + 4];
        al[3] = Xl[(mrow + g + 8) * 68 + kw0 + tig + 4];
        #pragma unroll
        for (int nt = 0; nt < 8; nt++) {
            const int nr = nbase + nt * 8 + g;
            const unsigned int bh0 = __ldg(&g_w2hi[nr * 64 + kw0 + tig]);
            const unsigned int bh1 = __ldg(&g_w2hi[nr * 64 + kw0 + tig + 4]);
            const unsigned int bl0 = __ldg(&g_w2lo[nr * 64 + kw0 + tig]);
            const unsigned int bl1 = __ldg(&g_w2lo[nr * 64 + kw0 + tig + 4]);
            mma_bf16(c[nt], ah, bh0, bh1);
            mma_bf16(c[nt], al, bh0, bh1);
            mma_bf16(c[nt], ah, bl0, bl1);
        }
    }

    // epilogue: relu + ssq + store (rows guarded for the partial last tile)
    float lssq = 0.0f;
    const int r0 = base + mrow + g;
    const int r1 = r0 + 8;
    #pragma unroll
    for (int nt = 0; nt < 8; nt++) {
        const int n0 = nbase + nt * 8;
        float v0 = fmaxf(c[nt][0], 0.0f);
        float v1 = fmaxf(c[nt][1], 0.0f);
        float v2 = fmaxf(c[nt][2], 0.0f);
        float v3 = fmaxf(c[nt][3], 0.0f);
        if (r0 < N_DST) {
            lssq += v0 * v0 + v1 * v1;
            *(float2*)(out + (size_t)r0 * OUTD + n0 + 2 * tig) = make_float2(v0, v1);
        }
        if (r1 < N_DST) {
            lssq += v2 * v2 + v3 * v3;
            *(float2*)(out + (size_t)r1 * OUTD + n0 + 2 * tig) = make_float2(v2, v3);
        }
    }

    #pragma unroll
    for (int off = 16; off > 0; off >>= 1)
        lssq += __shfl_down_sync(0xFFFFFFFFu, lssq, off);
    if (lane == 0) wssq[warp] = lssq;
    __syncthreads();
    if (tid == 0) {
        float s = 0.0f;
        #pragma unroll
        for (int i = 0; i < 8; i++) s += wssq[i];
        atomicAdd(&g_ssq, (double)s);
    }
}

// ---------------------------------------------------------------------------
// K5: out *= 1/sqrt(g_ssq)
// ---------------------------------------------------------------------------
__global__ void k_scale(float* __restrict__ out) {
    const int i = blockIdx.x * blockDim.x + threadIdx.x;
    const int n4 = (N_DST * OUTD) / 4;
    if (i >= n4) return;
    const float inv = (float)(1.0 / sqrt(g_ssq));
    float4 v = ((float4*)out)[i];
    v.x *= inv; v.y *= inv; v.z *= inv; v.w *= inv;
    ((float4*)out)[i] = v;
}

// ---------------------------------------------------------------------------
extern "C" void kernel_launch(void* const* d_in, const int* in_sizes, int n_in,
                              void* d_out, int out_size) {
    const float* h_src = (const float*)d_in[0];
    const float* h_dst = (const float*)d_in[1];
    const float* ew    = (const float*)d_in[2];
    const float* W1    = (const float*)d_in[3];
    const float* b1    = (const float*)d_in[4];
    const float* W2    = (const float*)d_in[5];
    const float* b2    = (const float*)d_in[6];
    const int*   src   = (const int*)d_in[7];
    const int*   dst   = (const int*)d_in[8];
    float* out = (float*)d_out;

    k_prep<<<128, 256>>>(W2);
    k_fc1<<<(N_SRC + 63) / 64, 256>>>(h_src, W1, b1);
    k_bucket<<<(N_EDGES + 255) / 256, 256>>>(ew, src, dst);
    k_gather<<<296, 256>>>(h_dst);
    k_fc2<<<(N_DST + 63) / 64, 256>>>(b2, out);
    k_scale<<<(N_DST * OUTD / 4 + 255) / 256, 256>>>(out);
}

// round 13
// speedup vs baseline: 1.2262x; 1.2262x over previous
#include <cuda_runtime.h>
#include <cuda_bf16.h>

#define N_SRC   100000
#define N_DST   100000
#define N_EDGES 1250000
#define D_FEAT  64
#define HIDDEN  64
#define OUTD    128
#define CAP     48      // P(Poisson(12.5) > 48) ~ 1e-14 per bin

// Scratch (alloc-free rule: __device__ globals)
__device__ float              g_hs[N_SRC * HIDDEN];
__device__ int                g_cnt[N_DST];
__device__ unsigned long long g_bkt[(size_t)N_DST * CAP];   // (w_bits<<32 | src)
__device__ unsigned int       g_xhi[(size_t)N_DST * 64];    // X hi-plane, bf16x2 words
__device__ unsigned int       g_xlo[(size_t)N_DST * 64];    // X lo-plane
__device__ unsigned int       g_w2hi[OUTD * 64];            // W2^T hi-plane [n][kw]
__device__ unsigned int       g_w2lo[OUTD * 64];
__device__ double             g_ssq;

__device__ __forceinline__ unsigned int packbf2(float a, float b) {
    __nv_bfloat162 t = __floats2bfloat162_rn(a, b);   // a -> low half
    return *(unsigned int*)&t;
}

__device__ __forceinline__ void mma_bf16(float* c, const unsigned int* a,
                                         unsigned int b0, unsigned int b1) {
    asm volatile(
        "mma.sync.aligned.m16n8k16.row.col.f32.bf16.bf16.f32 "
        "{%0,%1,%2,%3}, {%4,%5,%6,%7}, {%8,%9}, {%0,%1,%2,%3};"
        : "+f"(c[0]), "+f"(c[1]), "+f"(c[2]), "+f"(c[3])
        : "r"(a[0]), "r"(a[1]), "r"(a[2]), "r"(a[3]), "r"(b0), "r"(b1));
}

// ---------------------------------------------------------------------------
// K0: zero counts/ssq + convert W2^T to bf16 hi/lo planes (once).
// ---------------------------------------------------------------------------
__global__ void k_prep(const float* __restrict__ W2) {
    const int gt = blockIdx.x * blockDim.x + threadIdx.x;
    const int gs = gridDim.x * blockDim.x;
    for (int i = gt; i < N_DST / 4; i += gs)
        ((int4*)g_cnt)[i] = make_int4(0, 0, 0, 0);
    for (int i = gt; i < OUTD * 64; i += gs) {
        const int n = i >> 6, kw = i & 63;
        const float w0 = W2[(2 * kw) * OUTD + n];
        const float w1 = W2[(2 * kw + 1) * OUTD + n];
        const float h0 = __bfloat162float(__float2bfloat16(w0));
        const float h1 = __bfloat162float(__float2bfloat16(w1));
        g_w2hi[i] = packbf2(h0, h1);
        g_w2lo[i] = packbf2(w0 - h0, w1 - h1);
    }
    if (gt == 0) g_ssq = 0.0;
}

// ---------------------------------------------------------------------------
// K1: hs = relu(h_src @ W1 + b1). 64-row tiles; thread = 4 rows x 4 outputs.
// ---------------------------------------------------------------------------
__global__ void k_fc1(const float* __restrict__ h_src,
                      const float* __restrict__ W1,
                      const float* __restrict__ b1) {
    __shared__ float w1s[D_FEAT * HIDDEN];   // [k][o]
    __shared__ float b1s[HIDDEN];
    __shared__ float xs[64 * 68];            // [row][k], pad 68

    const int tid = threadIdx.x;
    for (int i = tid; i < D_FEAT * HIDDEN; i += blockDim.x) w1s[i] = W1[i];
    if (tid < HIDDEN) b1s[tid] = b1[tid];

    const int base = blockIdx.x * 64;
    for (int i = tid; i < 64 * 64; i += blockDim.x) {
        const int row = i >> 6, k = i & 63;
        const int rr = base + row;
        xs[row * 68 + k] = (rr < N_SRC) ? h_src[(size_t)rr * D_FEAT + k] : 0.0f;
    }
    __syncthreads();

    const int og   = tid & 15;    // output group: cols og*4..+3
    const int rgrp = tid >> 4;    // row group: rows rgrp*4..+3
    float acc[4][4];
    #pragma unroll
    for (int j = 0; j < 4; j++)
        #pragma unroll
        for (int q = 0; q < 4; q++) acc[j][q] = b1s[og * 4 + q];

    #pragma unroll 16
    for (int k = 0; k < D_FEAT; k++) {
        const float4 w4 = *(const float4*)&w1s[k * HIDDEN + og * 4];
        #pragma unroll
        for (int j = 0; j < 4; j++) {
            const float x = xs[(rgrp * 4 + j) * 68 + k];
            acc[j][0] = fmaf(x, w4.x, acc[j][0]);
            acc[j][1] = fmaf(x, w4.y, acc[j][1]);
            acc[j][2] = fmaf(x, w4.z, acc[j][2]);
            acc[j][3] = fmaf(x, w4.w, acc[j][3]);
        }
    }
    #pragma unroll
    for (int j = 0; j < 4; j++) {
        const int row = base + rgrp * 4 + j;
        if (row < N_SRC) {
            float4 o;
            o.x = fmaxf(acc[j][0], 0.0f);
            o.y = fmaxf(acc[j][1], 0.0f);
            o.z = fmaxf(acc[j][2], 0.0f);
            o.w = fmaxf(acc[j][3], 0.0f);
            *(float4*)&g_hs[(size_t)row * HIDDEN + og * 4] = o;
        }
    }
}

// ---------------------------------------------------------------------------
// K2: bucket edges by destination (int atomics only)   (R4-proven)
// ---------------------------------------------------------------------------
__global__ void k_bucket(const float* __restrict__ ew,
                         const int*   __restrict__ src_idx,
                         const int*   __restrict__ dst_idx) {
    const int e = blockIdx.x * blockDim.x + threadIdx.x;
    if (e >= N_EDGES) return;
    const int   s = __ldg(src_idx + e);
    const int   d = __ldg(dst_idx + e);
    const float w = __ldg(ew + e);
    const int slot = atomicAdd(&g_cnt[d], 1);
    if (slot < CAP) {
        const unsigned long long p =
            ((unsigned long long)__float_as_uint(w) << 32) | (unsigned int)s;
        g_bkt[(size_t)d * CAP + slot] = p;
    }
}

// ---------------------------------------------------------------------------
// K3: gather-reduce -> X bf16 hi/lo planes in global.
// Warp handles 4 dsts. FULL grid (3125 blocks): 40 warps/SM resident
// (48-reg limit), ~4 waves -> latency properly hidden.
// ---------------------------------------------------------------------------
__global__ void k_gather(const float* __restrict__ h_dst) {
    const int warp = threadIdx.x >> 5;
    const int lane = threadIdx.x & 31;

    for (int base = (blockIdx.x * 8 + warp) * 4; base < N_DST;
         base += gridDim.x * 8 * 4) {
        int n[4];
        unsigned long long e0[4], e1[4];
        #pragma unroll
        for (int r = 0; r < 4; r++) {
            const int dst = base + r;
            int c = __ldg(&g_cnt[dst]);
            n[r] = (c > CAP) ? CAP : c;
            const unsigned long long* bkt = g_bkt + (size_t)dst * CAP;
            e0[r] = (lane      < n[r]) ? __ldg(bkt + lane)      : 0ull;
            e1[r] = (lane + 32 < n[r]) ? __ldg(bkt + lane + 32) : 0ull;
        }
        #pragma unroll
        for (int r = 0; r < 4; r++) {
            float ax = 0.0f, ay = 0.0f, wsum = 0.0f;
            const int n0 = (n[r] < 32) ? n[r] : 32;
            for (int i = 0; i < n0; i++) {
                const unsigned long long p = __shfl_sync(0xFFFFFFFFu, e0[r], i);
                const float w = __uint_as_float((unsigned int)(p >> 32));
                const int   s = (int)(p & 0xffffffffu);
                const float2 v = __ldg(((const float2*)(g_hs + (size_t)s * HIDDEN)) + lane);
                ax = fmaf(v.x, w, ax);
                ay = fmaf(v.y, w, ay);
                wsum += w;
            }
            for (int i = 32; i < n[r]; i++) {
                const unsigned long long p = __shfl_sync(0xFFFFFFFFu, e1[r], i - 32);
                const float w = __uint_as_float((unsigned int)(p >> 32));
                const int   s = (int)(p & 0xffffffffu);
                const float2 v = __ldg(((const float2*)(g_hs + (size_t)s * HIDDEN)) + lane);
                ax = fmaf(v.x, w, ax);
                ay = fmaf(v.y, w, ay);
                wsum += w;
            }
            const int dst = base + r;
            const float inv = 1.0f / fmaxf(wsum, 1.0f);
            const float vx = ax * inv, vy = ay * inv;
            const float2 hd = __ldg(((const float2*)(h_dst + (size_t)dst * D_FEAT)) + lane);
            const float hx = __bfloat162float(__float2bfloat16(vx));
            const float hy = __bfloat162float(__float2bfloat16(vy));
            const float dx = __bfloat162float(__float2bfloat16(hd.x));
            const float dy = __bfloat162float(__float2bfloat16(hd.y));
            // word kw packs cols 2kw,2kw+1: nv -> words [0,32), h_dst -> [32,64)
            g_xhi[(size_t)dst * 64 + lane]      = packbf2(hx, hy);
            g_xlo[(size_t)dst * 64 + lane]      = packbf2(vx - hx, vy - hy);
            g_xhi[(size_t)dst * 64 + 32 + lane] = packbf2(dx, dy);
            g_xlo[(size_t)dst * 64 + 32 + lane] = packbf2(hd.x - dx, hd.y - dy);
        }
    }
}

// ---------------------------------------------------------------------------
// K4: fc2 streaming GEMM: out = relu(X @ W2 + b2), ssq accumulate.
// Block = 64-row tile; warp = 16 rows x 64 cols; bf16 mma 3-term split.
// ---------------------------------------------------------------------------
__global__ void k_fc2(const float* __restrict__ b2, float* __restrict__ out) {
    __shared__ unsigned int Xh[64 * 68];   // [row][kw], pad 68
    __shared__ unsigned int Xl[64 * 68];
    __shared__ float b2s[OUTD];
    __shared__ float wssq[8];

    const int tid  = threadIdx.x;
    const int base = blockIdx.x * 64;
    const int rows = (N_DST - base < 64) ? (N_DST - base) : 64;

    for (int i = tid; i < rows * 64; i += blockDim.x) {
        const int row = i >> 6, kw = i & 63;
        Xh[row * 68 + kw] = g_xhi[(size_t)(base + row) * 64 + kw];
        Xl[row * 68 + kw] = g_xlo[(size_t)(base + row) * 64 + kw];
    }
    if (tid < OUTD) b2s[tid] = b2[tid];
    __syncthreads();

    const int warp  = tid >> 5;
    const int lane  = tid & 31;
    const int g     = lane >> 2;
    const int tig   = lane & 3;
    const int mrow  = (warp & 3) * 16;       // row band
    const int nbase = (warp >> 2) * 64;      // col half

    float c[8][4];
    #pragma unroll
    for (int nt = 0; nt < 8; nt++) {
        const int n0 = nbase + nt * 8;
        c[nt][0] = b2s[n0 + 2 * tig];
        c[nt][1] = b2s[n0 + 2 * tig + 1];
        c[nt][2] = c[nt][0];
        c[nt][3] = c[nt][1];
    }

    #pragma unroll
    for (int kt = 0; kt < 8; kt++) {
        const int kw0 = kt * 8;
        unsigned int ah[4], al[4];
        ah[0] = Xh[(mrow + g) * 68 + kw0 + tig];
        ah[1] = Xh[(mrow + g + 8) * 68 + kw0 + tig];
        ah[2] = Xh[(mrow + g) * 68 + kw0 + tig + 4];
        ah[3] = Xh[(mrow + g + 8) * 68 + kw0 + tig + 4];
        al[0] = Xl[(mrow + g) * 68 + kw0 + tig];
        al[1] = Xl[(mrow + g + 8) * 68 + kw0 + tig];
        al[2] = Xl[(mrow + g) * 68 + kw0 + tig + 4];
        al[3] = Xl[(mrow + g + 8) * 68 + kw0 + tig + 4];
        #pragma unroll
        for (int nt = 0; nt < 8; nt++) {
            const int nr = nbase + nt * 8 + g;
            const unsigned int bh0 = __ldg(&g_w2hi[nr * 64 + kw0 + tig]);
            const unsigned int bh1 = __ldg(&g_w2hi[nr * 64 + kw0 + tig + 4]);
            const unsigned int bl0 = __ldg(&g_w2lo[nr * 64 + kw0 + tig]);
            const unsigned int bl1 = __ldg(&g_w2lo[nr * 64 + kw0 + tig + 4]);
            mma_bf16(c[nt], ah, bh0, bh1);
            mma_bf16(c[nt], al, bh0, bh1);
            mma_bf16(c[nt], ah, bl0, bl1);
        }
    }

    // epilogue: relu + ssq + store (rows guarded for the partial last tile)
    float lssq = 0.0f;
    const int r0 = base + mrow + g;
    const int r1 = r0 + 8;
    #pragma unroll
    for (int nt = 0; nt < 8; nt++) {
        const int n0 = nbase + nt * 8;
        float v0 = fmaxf(c[nt][0], 0.0f);
        float v1 = fmaxf(c[nt][1], 0.0f);
        float v2 = fmaxf(c[nt][2], 0.0f);
        float v3 = fmaxf(c[nt][3], 0.0f);
        if (r0 < N_DST) {
            lssq += v0 * v0 + v1 * v1;
            *(float2*)(out + (size_t)r0 * OUTD + n0 + 2 * tig) = make_float2(v0, v1);
        }
        if (r1 < N_DST) {
            lssq += v2 * v2 + v3 * v3;
            *(float2*)(out + (size_t)r1 * OUTD + n0 + 2 * tig) = make_float2(v2, v3);
        }
    }

    #pragma unroll
    for (int off = 16; off > 0; off >>= 1)
        lssq += __shfl_down_sync(0xFFFFFFFFu, lssq, off);
    if (lane == 0) wssq[warp] = lssq;
    __syncthreads();
    if (tid == 0) {
        float s = 0.0f;
        #pragma unroll
        for (int i = 0; i < 8; i++) s += wssq[i];
        atomicAdd(&g_ssq, (double)s);
    }
}

// ---------------------------------------------------------------------------
// K5: out *= 1/sqrt(g_ssq)
// ---------------------------------------------------------------------------
__global__ void k_scale(float* __restrict__ out) {
    const int i = blockIdx.x * blockDim.x + threadIdx.x;
    const int n4 = (N_DST * OUTD) / 4;
    if (i >= n4) return;
    const float inv = (float)(1.0 / sqrt(g_ssq));
    float4 v = ((float4*)out)[i];
    v.x *= inv; v.y *= inv; v.z *= inv; v.w *= inv;
    ((float4*)out)[i] = v;
}

// ---------------------------------------------------------------------------
extern "C" void kernel_launch(void* const* d_in, const int* in_sizes, int n_in,
                              void* d_out, int out_size) {
    const float* h_src = (const float*)d_in[0];
    const float* h_dst = (const float*)d_in[1];
    const float* ew    = (const float*)d_in[2];
    const float* W1    = (const float*)d_in[3];
    const float* b1    = (const float*)d_in[4];
    const float* W2    = (const float*)d_in[5];
    const float* b2    = (const float*)d_in[6];
    const int*   src   = (const int*)d_in[7];
    const int*   dst   = (const int*)d_in[8];
    float* out = (float*)d_out;

    k_prep<<<128, 256>>>(W2);
    k_fc1<<<(N_SRC + 63) / 64, 256>>>(h_src, W1, b1);
    k_bucket<<<(N_EDGES + 255) / 256, 256>>>(ew, src, dst);
    // FULL grid: one 4-dst task per warp (25000 warps -> 3125 blocks)
    k_gather<<<(N_DST + 31) / 32, 256>>>(h_dst);
    k_fc2<<<(N_DST + 63) / 64, 256>>>(b2, out);
    k_scale<<<(N_DST * OUTD / 4 + 255) / 256, 256>>>(out);
}

// round 15
// speedup vs baseline: 1.2615x; 1.0288x over previous
#include <cuda_runtime.h>
#include <cuda_bf16.h>

#define N_SRC   100000
#define N_DST   100000
#define N_EDGES 1250000
#define D_FEAT  64
#define HIDDEN  64
#define OUTD    128
#define CAP     48      // P(Poisson(12.5) > 48) ~ 1e-14 per bin

// Scratch (alloc-free rule: __device__ globals)
__device__ float              g_hs[N_SRC * HIDDEN];
__device__ int                g_cnt[N_DST];
__device__ unsigned long long g_bkt[(size_t)N_DST * CAP];   // (w_bits<<32 | src)
__device__ unsigned int       g_xhi[(size_t)N_DST * 64];    // X hi-plane, bf16x2 words
__device__ unsigned int       g_xlo[(size_t)N_DST * 64];    // X lo-plane
__device__ unsigned int       g_w2hi[OUTD * 64];            // W2^T hi-plane [n][kw]
__device__ unsigned int       g_w2lo[OUTD * 64];
__device__ double             g_ssq;

__device__ __forceinline__ unsigned int packbf2(float a, float b) {
    __nv_bfloat162 t = __floats2bfloat162_rn(a, b);   // a -> low half
    return *(unsigned int*)&t;
}

__device__ __forceinline__ void mma_bf16(float* c, const unsigned int* a,
                                         unsigned int b0, unsigned int b1) {
    asm volatile(
        "mma.sync.aligned.m16n8k16.row.col.f32.bf16.bf16.f32 "
        "{%0,%1,%2,%3}, {%4,%5,%6,%7}, {%8,%9}, {%0,%1,%2,%3};"
        : "+f"(c[0]), "+f"(c[1]), "+f"(c[2]), "+f"(c[3])
        : "r"(a[0]), "r"(a[1]), "r"(a[2]), "r"(a[3]), "r"(b0), "r"(b1));
}

// ---------------------------------------------------------------------------
// K0: zero counts/ssq + convert W2^T to bf16 hi/lo planes (once).
// ---------------------------------------------------------------------------
__global__ void k_prep(const float* __restrict__ W2) {
    const int gt = blockIdx.x * blockDim.x + threadIdx.x;
    const int gs = gridDim.x * blockDim.x;
    for (int i = gt; i < N_DST / 4; i += gs)
        ((int4*)g_cnt)[i] = make_int4(0, 0, 0, 0);
    for (int i = gt; i < OUTD * 64; i += gs) {
        const int n = i >> 6, kw = i & 63;
        const float w0 = W2[(2 * kw) * OUTD + n];
        const float w1 = W2[(2 * kw + 1) * OUTD + n];
        const float h0 = __bfloat162float(__float2bfloat16(w0));
        const float h1 = __bfloat162float(__float2bfloat16(w1));
        g_w2hi[i] = packbf2(h0, h1);
        g_w2lo[i] = packbf2(w0 - h0, w1 - h1);
    }
    if (gt == 0) g_ssq = 0.0;
}

// ---------------------------------------------------------------------------
// K1: hs = relu(h_src @ W1 + b1). 64-row tiles; thread = 4 rows x 4 outputs.
// ---------------------------------------------------------------------------
__global__ void k_fc1(const float* __restrict__ h_src,
                      const float* __restrict__ W1,
                      const float* __restrict__ b1) {
    __shared__ float w1s[D_FEAT * HIDDEN];   // [k][o]
    __shared__ float b1s[HIDDEN];
    __shared__ float xs[64 * 68];            // [row][k], pad 68

    const int tid = threadIdx.x;
    for (int i = tid; i < D_FEAT * HIDDEN; i += blockDim.x) w1s[i] = W1[i];
    if (tid < HIDDEN) b1s[tid] = b1[tid];

    const int base = blockIdx.x * 64;
    for (int i = tid; i < 64 * 64; i += blockDim.x) {
        const int row = i >> 6, k = i & 63;
        const int rr = base + row;
        xs[row * 68 + k] = (rr < N_SRC) ? h_src[(size_t)rr * D_FEAT + k] : 0.0f;
    }
    __syncthreads();

    const int og   = tid & 15;    // output group: cols og*4..+3
    const int rgrp = tid >> 4;    // row group: rows rgrp*4..+3
    float acc[4][4];
    #pragma unroll
    for (int j = 0; j < 4; j++)
        #pragma unroll
        for (int q = 0; q < 4; q++) acc[j][q] = b1s[og * 4 + q];

    #pragma unroll 16
    for (int k = 0; k < D_FEAT; k++) {
        const float4 w4 = *(const float4*)&w1s[k * HIDDEN + og * 4];
        #pragma unroll
        for (int j = 0; j < 4; j++) {
            const float x = xs[(rgrp * 4 + j) * 68 + k];
            acc[j][0] = fmaf(x, w4.x, acc[j][0]);
            acc[j][1] = fmaf(x, w4.y, acc[j][1]);
            acc[j][2] = fmaf(x, w4.z, acc[j][2]);
            acc[j][3] = fmaf(x, w4.w, acc[j][3]);
        }
    }
    #pragma unroll
    for (int j = 0; j < 4; j++) {
        const int row = base + rgrp * 4 + j;
        if (row < N_SRC) {
            float4 o;
            o.x = fmaxf(acc[j][0], 0.0f);
            o.y = fmaxf(acc[j][1], 0.0f);
            o.z = fmaxf(acc[j][2], 0.0f);
            o.w = fmaxf(acc[j][3], 0.0f);
            *(float4*)&g_hs[(size_t)row * HIDDEN + og * 4] = o;
        }
    }
}

// ---------------------------------------------------------------------------
// K2: bucket edges by destination (int atomics only)   (R4-proven)
// ---------------------------------------------------------------------------
__global__ void k_bucket(const float* __restrict__ ew,
                         const int*   __restrict__ src_idx,
                         const int*   __restrict__ dst_idx) {
    const int e = blockIdx.x * blockDim.x + threadIdx.x;
    if (e >= N_EDGES) return;
    const int   s = __ldg(src_idx + e);
    const int   d = __ldg(dst_idx + e);
    const float w = __ldg(ew + e);
    const int slot = atomicAdd(&g_cnt[d], 1);
    if (slot < CAP) {
        const unsigned long long p =
            ((unsigned long long)__float_as_uint(w) << 32) | (unsigned int)s;
        g_bkt[(size_t)d * CAP + slot] = p;
    }
}

// ---------------------------------------------------------------------------
// K3: gather-reduce -> X bf16 hi/lo planes in global.
// Full grid (one 4-dst task per warp) + chunk-of-4 independent predicated
// loads (R8-proven numerics) -> MLP 4 per warp, latency fully covered.
// ---------------------------------------------------------------------------
__global__ void k_gather(const float* __restrict__ h_dst) {
    const int warp = threadIdx.x >> 5;
    const int lane = threadIdx.x & 31;

    for (int base = (blockIdx.x * 8 + warp) * 4; base < N_DST;
         base += gridDim.x * 8 * 4) {
        int n[4];
        unsigned long long e0[4], e1[4];
        #pragma unroll
        for (int r = 0; r < 4; r++) {
            const int dst = base + r;
            int c = __ldg(&g_cnt[dst]);
            n[r] = (c > CAP) ? CAP : c;
            const unsigned long long* bkt = g_bkt + (size_t)dst * CAP;
            e0[r] = (lane      < n[r]) ? __ldg(bkt + lane)      : 0ull;
            e1[r] = (lane + 32 < n[r]) ? __ldg(bkt + lane + 32) : 0ull;
        }
        #pragma unroll
        for (int r = 0; r < 4; r++) {
            float ax = 0.0f, ay = 0.0f, wsum = 0.0f;
            const int nr = n[r];
            for (int i = 0; i < nr; i += 4) {
                float2 v[4];
                float  w[4];
                #pragma unroll
                for (int j = 0; j < 4; j++) {
                    const int idx = i + j;                       // uniform
                    unsigned long long p;
                    if (idx < 32) p = __shfl_sync(0xFFFFFFFFu, e0[r], idx);
                    else          p = __shfl_sync(0xFFFFFFFFu, e1[r], idx - 32);
                    const bool act = idx < nr;                   // uniform
                    w[j] = act ? __uint_as_float((unsigned int)(p >> 32)) : 0.0f;
                    const int s = (int)(p & 0xffffffffu);
                    v[j] = act
                        ? __ldg(((const float2*)(g_hs + (size_t)s * HIDDEN)) + lane)
                        : make_float2(0.0f, 0.0f);
                }
                #pragma unroll
                for (int j = 0; j < 4; j++) {
                    ax = fmaf(v[j].x, w[j], ax);
                    ay = fmaf(v[j].y, w[j], ay);
                    wsum += w[j];
                }
            }
            const int dst = base + r;
            const float inv = 1.0f / fmaxf(wsum, 1.0f);
            const float vx = ax * inv, vy = ay * inv;
            const float2 hd = __ldg(((const float2*)(h_dst + (size_t)dst * D_FEAT)) + lane);
            const float hx = __bfloat162float(__float2bfloat16(vx));
            const float hy = __bfloat162float(__float2bfloat16(vy));
            const float dx = __bfloat162float(__float2bfloat16(hd.x));
            const float dy = __bfloat162float(__float2bfloat16(hd.y));
            // word kw packs cols 2kw,2kw+1: nv -> words [0,32), h_dst -> [32,64)
            g_xhi[(size_t)dst * 64 + lane]      = packbf2(hx, hy);
            g_xlo[(size_t)dst * 64 + lane]      = packbf2(vx - hx, vy - hy);
            g_xhi[(size_t)dst * 64 + 32 + lane] = packbf2(dx, dy);
            g_xlo[(size_t)dst * 64 + 32 + lane] = packbf2(hd.x - dx, hd.y - dy);
        }
    }
}

// ---------------------------------------------------------------------------
// K4: fc2 streaming GEMM: out = relu(X @ W2 + b2), ssq accumulate.
// Block = 64-row tile; warp = 16 rows x 64 cols; bf16 mma 3-term split.
// ---------------------------------------------------------------------------
__global__ void k_fc2(const float* __restrict__ b2, float* __restrict__ out) {
    __shared__ unsigned int Xh[64 * 68];   // [row][kw], pad 68
    __shared__ unsigned int Xl[64 * 68];
    __shared__ float b2s[OUTD];
    __shared__ float wssq[8];

    const int tid  = threadIdx.x;
    const int base = blockIdx.x * 64;
    const int rows = (N_DST - base < 64) ? (N_DST - base) : 64;

    for (int i = tid; i < rows * 64; i += blockDim.x) {
        const int row = i >> 6, kw = i & 63;
        Xh[row * 68 + kw] = g_xhi[(size_t)(base + row) * 64 + kw];
        Xl[row * 68 + kw] = g_xlo[(size_t)(base + row) * 64 + kw];
    }
    if (tid < OUTD) b2s[tid] = b2[tid];
    __syncthreads();

    const int warp  = tid >> 5;
    const int lane  = tid & 31;
    const int g     = lane >> 2;
    const int tig   = lane & 3;
    const int mrow  = (warp & 3) * 16;       // row band
    const int nbase = (warp >> 2) * 64;      // col half

    float c[8][4];
    #pragma unroll
    for (int nt = 0; nt < 8; nt++) {
        const int n0 = nbase + nt * 8;
        c[nt][0] = b2s[n0 + 2 * tig];
        c[nt][1] = b2s[n0 + 2 * tig + 1];
        c[nt][2] = c[nt][0];
        c[nt][3] = c[nt][1];
    }

    #pragma unroll
    for (int kt = 0; kt < 8; kt++) {
        const int kw0 = kt * 8;
        unsigned int ah[4], al[4];
        ah[0] = Xh[(mrow + g) * 68 + kw0 + tig];
        ah[1] = Xh[(mrow + g + 8) * 68 + kw0 + tig];
        ah[2] = Xh[(mrow + g) * 68 + kw0 + tig + 4];
        ah[3] = Xh[(mrow + g + 8) * 68 + kw0 + tig + 4];
        al[0] = Xl[(mrow + g) * 68 + kw0 + tig];
        al[1] = Xl[(mrow + g + 8) * 68 + kw0 + tig];
        al[2] = Xl[(mrow + g) * 68 + kw0 + tig + 4];
        al[3] = Xl[(mrow + g + 8) * 68 + kw0 + tig + 4];
        #pragma unroll
        for (int nt = 0; nt < 8; nt++) {
            const int nr = nbase + nt * 8 + g;
            const unsigned int bh0 = __ldg(&g_w2hi[nr * 64 + kw0 + tig]);
            const unsigned int bh1 = __ldg(&g_w2hi[nr * 64 + kw0 + tig + 4]);
            const unsigned int bl0 = __ldg(&g_w2lo[nr * 64 + kw0 + tig]);
            const unsigned int bl1 = __ldg(&g_w2lo[nr * 64 + kw0 + tig + 4]);
            mma_bf16(c[nt], ah, bh0, bh1);
            mma_bf16(c[nt], al, bh0, bh1);
            mma_bf16(c[nt], ah, bl0, bl1);
        }
    }

    // epilogue: relu + ssq + store (rows guarded for the partial last tile)
    float lssq = 0.0f;
    const int r0 = base + mrow + g;
    const int r1 = r0 + 8;
    #pragma unroll
    for (int nt = 0; nt < 8; nt++) {
        const int n0 = nbase + nt * 8;
        float v0 = fmaxf(c[nt][0], 0.0f);
        float v1 = fmaxf(c[nt][1], 0.0f);
        float v2 = fmaxf(c[nt][2], 0.0f);
        float v3 = fmaxf(c[nt][3], 0.0f);
        if (r0 < N_DST) {
            lssq += v0 * v0 + v1 * v1;
            *(float2*)(out + (size_t)r0 * OUTD + n0 + 2 * tig) = make_float2(v0, v1);
        }
        if (r1 < N_DST) {
            lssq += v2 * v2 + v3 * v3;
            *(float2*)(out + (size_t)r1 * OUTD + n0 + 2 * tig) = make_float2(v2, v3);
        }
    }

    #pragma unroll
    for (int off = 16; off > 0; off >>= 1)
        lssq += __shfl_down_sync(0xFFFFFFFFu, lssq, off);
    if (lane == 0) wssq[warp] = lssq;
    __syncthreads();
    if (tid == 0) {
        float s = 0.0f;
        #pragma unroll
        for (int i = 0; i < 8; i++) s += wssq[i];
        atomicAdd(&g_ssq, (double)s);
    }
}

// ---------------------------------------------------------------------------
// K5: out *= 1/sqrt(g_ssq)
// ---------------------------------------------------------------------------
__global__ void k_scale(float* __restrict__ out) {
    const int i = blockIdx.x * blockDim.x + threadIdx.x;
    const int n4 = (N_DST * OUTD) / 4;
    if (i >= n4) return;
    const float inv = (float)(1.0 / sqrt(g_ssq));
    float4 v = ((float4*)out)[i];
    v.x *= inv; v.y *= inv; v.z *= inv; v.w *= inv;
    ((float4*)out)[i] = v;
}

// ---------------------------------------------------------------------------
extern "C" void kernel_launch(void* const* d_in, const int* in_sizes, int n_in,
                              void* d_out, int out_size) {
    const float* h_src = (const float*)d_in[0];
    const float* h_dst = (const float*)d_in[1];
    const float* ew    = (const float*)d_in[2];
    const float* W1    = (const float*)d_in[3];
    const float* b1    = (const float*)d_in[4];
    const float* W2    = (const float*)d_in[5];
    const float* b2    = (const float*)d_in[6];
    const int*   src   = (const int*)d_in[7];
    const int*   dst   = (const int*)d_in[8];
    float* out = (float*)d_out;

    k_prep<<<128, 256>>>(W2);
    k_fc1<<<(N_SRC + 63) / 64, 256>>>(h_src, W1, b1);
    k_bucket<<<(N_EDGES + 255) / 256, 256>>>(ew, src, dst);
    // FULL grid: one 4-dst task per warp (25000 warps -> 3125 blocks)
    k_gather<<<(N_DST + 31) / 32, 256>>>(h_dst);
    k_fc2<<<(N_DST + 63) / 64, 256>>>(b2, out);
    k_scale<<<(N_DST * OUTD / 4 + 255) / 256, 256>>>(out);
}

// round 17
// speedup vs baseline: 1.3469x; 1.0677x over previous
#include <cuda_runtime.h>
#include <cuda_bf16.h>

#define N_SRC   100000
#define N_DST   100000
#define N_EDGES 1250000
#define D_FEAT  64
#define HIDDEN  64
#define OUTD    128
#define CAP     48      // P(Poisson(12.5) > 48) ~ 1e-14 per bin

#define FC1_GRID ((N_SRC + 63) / 64)        // 1563 fc1 tile blocks
#define BKT_GRID ((N_EDGES + 255) / 256)    // 4883 bucket blocks

// Scratch (alloc-free rule: __device__ globals)
__device__ float              g_hs[N_SRC * HIDDEN];
__device__ int                g_cnt[N_DST];
__device__ unsigned long long g_bkt[(size_t)N_DST * CAP];   // (w_bits<<32 | src)
__device__ unsigned int       g_xhi[(size_t)N_DST * 64];    // X hi-plane, bf16x2 words
__device__ unsigned int       g_xlo[(size_t)N_DST * 64];    // X lo-plane
__device__ unsigned int       g_w2hi[OUTD * 64];            // W2^T hi-plane [n][kw]
__device__ unsigned int       g_w2lo[OUTD * 64];
__device__ double             g_ssq;

__device__ __forceinline__ unsigned int packbf2(float a, float b) {
    __nv_bfloat162 t = __floats2bfloat162_rn(a, b);   // a -> low half
    return *(unsigned int*)&t;
}

__device__ __forceinline__ void mma_bf16(float* c, const unsigned int* a,
                                         unsigned int b0, unsigned int b1) {
    asm volatile(
        "mma.sync.aligned.m16n8k16.row.col.f32.bf16.bf16.f32 "
        "{%0,%1,%2,%3}, {%4,%5,%6,%7}, {%8,%9}, {%0,%1,%2,%3};"
        : "+f"(c[0]), "+f"(c[1]), "+f"(c[2]), "+f"(c[3])
        : "r"(a[0]), "r"(a[1]), "r"(a[2]), "r"(a[3]), "r"(b0), "r"(b1));
}

// ---------------------------------------------------------------------------
// K0: zero counts/ssq + convert W2^T to bf16 hi/lo planes (once).
// ---------------------------------------------------------------------------
__global__ void k_prep(const float* __restrict__ W2) {
    const int gt = blockIdx.x * blockDim.x + threadIdx.x;
    const int gs = gridDim.x * blockDim.x;
    for (int i = gt; i < N_DST / 4; i += gs)
        ((int4*)g_cnt)[i] = make_int4(0, 0, 0, 0);
    for (int i = gt; i < OUTD * 64; i += gs) {
        const int n = i >> 6, kw = i & 63;
        const float w0 = W2[(2 * kw) * OUTD + n];
        const float w1 = W2[(2 * kw + 1) * OUTD + n];
        const float h0 = __bfloat162float(__float2bfloat16(w0));
        const float h1 = __bfloat162float(__float2bfloat16(w1));
        g_w2hi[i] = packbf2(h0, h1);
        g_w2lo[i] = packbf2(w0 - h0, w1 - h1);
    }
    if (gt == 0) g_ssq = 0.0;
}

// ---------------------------------------------------------------------------
// K1: fused fc1 + bucket, FULL grids for both halves.
// blocks [0, FC1_GRID): fc1 64-row tile (thread = 4 rows x 4 outputs).
// blocks [FC1_GRID, FC1_GRID+BKT_GRID): bucket 256 edges (int atomics).
// ---------------------------------------------------------------------------
__global__ void k_fc1_bucket(const float* __restrict__ h_src,
                             const float* __restrict__ W1,
                             const float* __restrict__ b1,
                             const float* __restrict__ ew,
                             const int*   __restrict__ src_idx,
                             const int*   __restrict__ dst_idx) {
    if (blockIdx.x < FC1_GRID) {
        __shared__ float w1s[D_FEAT * HIDDEN];   // [k][o]
        __shared__ float b1s[HIDDEN];
        __shared__ float xs[64 * 68];            // [row][k], pad 68

        const int tid = threadIdx.x;
        for (int i = tid; i < D_FEAT * HIDDEN; i += blockDim.x) w1s[i] = W1[i];
        if (tid < HIDDEN) b1s[tid] = b1[tid];

        const int base = blockIdx.x * 64;
        for (int i = tid; i < 64 * 64; i += blockDim.x) {
            const int row = i >> 6, k = i & 63;
            const int rr = base + row;
            xs[row * 68 + k] = (rr < N_SRC) ? h_src[(size_t)rr * D_FEAT + k] : 0.0f;
        }
        __syncthreads();

        const int og   = tid & 15;    // output cols og*4..+3
        const int rgrp = tid >> 4;    // rows rgrp*4..+3
        float acc[4][4];
        #pragma unroll
        for (int j = 0; j < 4; j++)
            #pragma unroll
            for (int q = 0; q < 4; q++) acc[j][q] = b1s[og * 4 + q];

        #pragma unroll 16
        for (int k = 0; k < D_FEAT; k++) {
            const float4 w4 = *(const float4*)&w1s[k * HIDDEN + og * 4];
            #pragma unroll
            for (int j = 0; j < 4; j++) {
                const float x = xs[(rgrp * 4 + j) * 68 + k];
                acc[j][0] = fmaf(x, w4.x, acc[j][0]);
                acc[j][1] = fmaf(x, w4.y, acc[j][1]);
                acc[j][2] = fmaf(x, w4.z, acc[j][2]);
                acc[j][3] = fmaf(x, w4.w, acc[j][3]);
            }
        }
        #pragma unroll
        for (int j = 0; j < 4; j++) {
            const int row = base + rgrp * 4 + j;
            if (row < N_SRC) {
                float4 o;
                o.x = fmaxf(acc[j][0], 0.0f);
                o.y = fmaxf(acc[j][1], 0.0f);
                o.z = fmaxf(acc[j][2], 0.0f);
                o.w = fmaxf(acc[j][3], 0.0f);
                *(float4*)&g_hs[(size_t)row * HIDDEN + og * 4] = o;
            }
        }
    } else {
        const int e = (blockIdx.x - FC1_GRID) * blockDim.x + threadIdx.x;
        if (e < N_EDGES) {
            const int   s = __ldg(src_idx + e);
            const int   d = __ldg(dst_idx + e);
            const float w = __ldg(ew + e);
            const int slot = atomicAdd(&g_cnt[d], 1);
            if (slot < CAP) {
                const unsigned long long p =
                    ((unsigned long long)__float_as_uint(w) << 32) | (unsigned int)s;
                g_bkt[(size_t)d * CAP + slot] = p;
            }
        }
    }
}

// ---------------------------------------------------------------------------
// K2: gather-reduce -> X bf16 hi/lo planes in global.
// Entry distribution via broadcast __ldg (L1-resident bucket rows): no
// shuffles, no selects; full chunks of 4 (MLP 4) + serial tail.
// Accumulation order identical to R15 -> same numerics.
// ---------------------------------------------------------------------------
__global__ void k_gather(const float* __restrict__ h_dst) {
    const int warp = threadIdx.x >> 5;
    const int lane = threadIdx.x & 31;

    for (int base = (blockIdx.x * 8 + warp) * 4; base < N_DST;
         base += gridDim.x * 8 * 4) {
        #pragma unroll
        for (int r = 0; r < 4; r++) {
            const int dst = base + r;
            int c = __ldg(&g_cnt[dst]);
            const int nr = (c > CAP) ? CAP : c;
            const unsigned long long* bkt = g_bkt + (size_t)dst * CAP;

            float ax = 0.0f, ay = 0.0f, wsum = 0.0f;
            int i = 0;
            const int nfull = nr & ~3;
            for (; i < nfull; i += 4) {
                float2 v[4];
                float  w[4];
                #pragma unroll
                for (int j = 0; j < 4; j++) {
                    const unsigned long long p = __ldg(bkt + i + j);  // broadcast
                    w[j] = __uint_as_float((unsigned int)(p >> 32));
                    const int s = (int)(p & 0xffffffffu);
                    v[j] = __ldg(((const float2*)(g_hs + (size_t)s * HIDDEN)) + lane);
                }
                #pragma unroll
                for (int j = 0; j < 4; j++) {
                    ax = fmaf(v[j].x, w[j], ax);
                    ay = fmaf(v[j].y, w[j], ay);
                    wsum += w[j];
                }
            }
            for (; i < nr; i++) {
                const unsigned long long p = __ldg(bkt + i);
                const float w = __uint_as_float((unsigned int)(p >> 32));
                const int s = (int)(p & 0xffffffffu);
                const float2 v = __ldg(((const float2*)(g_hs + (size_t)s * HIDDEN)) + lane);
                ax = fmaf(v.x, w, ax);
                ay = fmaf(v.y, w, ay);
                wsum += w;
            }

            const float inv = 1.0f / fmaxf(wsum, 1.0f);
            const float vx = ax * inv, vy = ay * inv;
            const float2 hd = __ldg(((const float2*)(h_dst + (size_t)dst * D_FEAT)) + lane);
            const float hx = __bfloat162float(__float2bfloat16(vx));
            const float hy = __bfloat162float(__float2bfloat16(vy));
            const float dx = __bfloat162float(__float2bfloat16(hd.x));
            const float dy = __bfloat162float(__float2bfloat16(hd.y));
            // word kw packs cols 2kw,2kw+1: nv -> words [0,32), h_dst -> [32,64)
            g_xhi[(size_t)dst * 64 + lane]      = packbf2(hx, hy);
            g_xlo[(size_t)dst * 64 + lane]      = packbf2(vx - hx, vy - hy);
            g_xhi[(size_t)dst * 64 + 32 + lane] = packbf2(dx, dy);
            g_xlo[(size_t)dst * 64 + 32 + lane] = packbf2(hd.x - dx, hd.y - dy);
        }
    }
}

// ---------------------------------------------------------------------------
// K3: fc2 streaming GEMM: out = relu(X @ W2 + b2), ssq accumulate.
// Block = 64-row tile; warp = 16 rows x 64 cols; bf16 mma 3-term split.
// ---------------------------------------------------------------------------
__global__ void k_fc2(const float* __restrict__ b2, float* __restrict__ out) {
    __shared__ unsigned int Xh[64 * 68];   // [row][kw], pad 68
    __shared__ unsigned int Xl[64 * 68];
    __shared__ float b2s[OUTD];
    __shared__ float wssq[8];

    const int tid  = threadIdx.x;
    const int base = blockIdx.x * 64;
    const int rows = (N_DST - base < 64) ? (N_DST - base) : 64;

    for (int i = tid; i < rows * 64; i += blockDim.x) {
        const int row = i >> 6, kw = i & 63;
        Xh[row * 68 + kw] = g_xhi[(size_t)(base + row) * 64 + kw];
        Xl[row * 68 + kw] = g_xlo[(size_t)(base + row) * 64 + kw];
    }
    if (tid < OUTD) b2s[tid] = b2[tid];
    __syncthreads();

    const int warp  = tid >> 5;
    const int lane  = tid & 31;
    const int g     = lane >> 2;
    const int tig   = lane & 3;
    const int mrow  = (warp & 3) * 16;       // row band
    const int nbase = (warp >> 2) * 64;      // col half

    float c[8][4];
    #pragma unroll
    for (int nt = 0; nt < 8; nt++) {
        const int n0 = nbase + nt * 8;
        c[nt][0] = b2s[n0 + 2 * tig];
        c[nt][1] = b2s[n0 + 2 * tig + 1];
        c[nt][2] = c[nt][0];
        c[nt][3] = c[nt][1];
    }

    #pragma unroll
    for (int kt = 0; kt < 8; kt++) {
        const int kw0 = kt * 8;
        unsigned int ah[4], al[4];
        ah[0] = Xh[(mrow + g) * 68 + kw0 + tig];
        ah[1] = Xh[(mrow + g + 8) * 68 + kw0 + tig];
        ah[2] = Xh[(mrow + g) * 68 + kw0 + tig + 4];
        ah[3] = Xh[(mrow + g + 8) * 68 + kw0 + tig + 4];
        al[0] = Xl[(mrow + g) * 68 + kw0 + tig];
        al[1] = Xl[(mrow + g + 8) * 68 + kw0 + tig];
        al[2] = Xl[(mrow + g) * 68 + kw0 + tig + 4];
        al[3] = Xl[(mrow + g + 8) * 68 + kw0 + tig + 4];
        #pragma unroll
        for (int nt = 0; nt < 8; nt++) {
            const int nr = nbase + nt * 8 + g;
            const unsigned int bh0 = __ldg(&g_w2hi[nr * 64 + kw0 + tig]);
            const unsigned int bh1 = __ldg(&g_w2hi[nr * 64 + kw0 + tig + 4]);
            const unsigned int bl0 = __ldg(&g_w2lo[nr * 64 + kw0 + tig]);
            const unsigned int bl1 = __ldg(&g_w2lo[nr * 64 + kw0 + tig + 4]);
            mma_bf16(c[nt], ah, bh0, bh1);
            mma_bf16(c[nt], al, bh0, bh1);
            mma_bf16(c[nt], ah, bl0, bl1);
        }
    }

    // epilogue: relu + ssq + store (rows guarded for the partial last tile)
    float lssq = 0.0f;
    const int r0 = base + mrow + g;
    const int r1 = r0 + 8;
    #pragma unroll
    for (int nt = 0; nt < 8; nt++) {
        const int n0 = nbase + nt * 8;
        float v0 = fmaxf(c[nt][0], 0.0f);
        float v1 = fmaxf(c[nt][1], 0.0f);
        float v2 = fmaxf(c[nt][2], 0.0f);
        float v3 = fmaxf(c[nt][3], 0.0f);
        if (r0 < N_DST) {
            lssq += v0 * v0 + v1 * v1;
            *(float2*)(out + (size_t)r0 * OUTD + n0 + 2 * tig) = make_float2(v0, v1);
        }
        if (r1 < N_DST) {
            lssq += v2 * v2 + v3 * v3;
            *(float2*)(out + (size_t)r1 * OUTD + n0 + 2 * tig) = make_float2(v2, v3);
        }
    }

    #pragma unroll
    for (int off = 16; off > 0; off >>= 1)
        lssq += __shfl_down_sync(0xFFFFFFFFu, lssq, off);
    if (lane == 0) wssq[warp] = lssq;
    __syncthreads();
    if (tid == 0) {
        float s = 0.0f;
        #pragma unroll
        for (int i = 0; i < 8; i++) s += wssq[i];
        atomicAdd(&g_ssq, (double)s);
    }
}

// ---------------------------------------------------------------------------
// K4: out *= 1/sqrt(g_ssq).  Two strided float4 per thread -> MLP 2.
// ---------------------------------------------------------------------------
__global__ void k_scale(float* __restrict__ out) {
    const int n4 = (N_DST * OUTD) / 4;            // 3.2M
    const int stride = gridDim.x * blockDim.x;    // n4/2
    const int i = blockIdx.x * blockDim.x + threadIdx.x;
    const float inv = (float)(1.0 / sqrt(g_ssq));
    float4* o4 = (float4*)out;
    if (i < n4) {
        float4 a = o4[i];
        const int i2 = i + stride;
        float4 b;
        if (i2 < n4) b = o4[i2];
        a.x *= inv; a.y *= inv; a.z *= inv; a.w *= inv;
        o4[i] = a;
        if (i2 < n4) {
            b.x *= inv; b.y *= inv; b.z *= inv; b.w *= inv;
            o4[i2] = b;
        }
    }
}

// ---------------------------------------------------------------------------
extern "C" void kernel_launch(void* const* d_in, const int* in_sizes, int n_in,
                              void* d_out, int out_size) {
    const float* h_src = (const float*)d_in[0];
    const float* h_dst = (const float*)d_in[1];
    const float* ew    = (const float*)d_in[2];
    const float* W1    = (const float*)d_in[3];
    const float* b1    = (const float*)d_in[4];
    const float* W2    = (const float*)d_in[5];
    const float* b2    = (const float*)d_in[6];
    const int*   src   = (const int*)d_in[7];
    const int*   dst   = (const int*)d_in[8];
    float* out = (float*)d_out;

    k_prep<<<128, 256>>>(W2);
    k_fc1_bucket<<<FC1_GRID + BKT_GRID, 256>>>(h_src, W1, b1, ew, src, dst);
    // one 4-dst task per warp (25000 warps -> 3125 blocks)
    k_gather<<<(N_DST + 31) / 32, 256>>>(h_dst);
    k_fc2<<<(N_DST + 63) / 64, 256>>>(b2, out);
    {
        const int n4 = (N_DST * OUTD) / 4;
        const int threads = n4 / 2;                       // 2 float4 per thread
        k_scale<<<(threads + 255) / 256, 256>>>(out);
    }
}